// round 15
// baseline (speedup 1.0000x reference)
#include <cuda_runtime.h>

// LIF, tau=2, hard reset to 0, decay_input=False:
//   v = (v + x_t) - v*0.5 ; s = (v>=1) ; out=s ; v = s?0:v
// Pure streaming: 268MB read + 268MB write, T=4 carried in registers.
// R12: Blackwell 256-bit global ld/st (ld/st.global.v8.f32 -> LDG.E.256 /
// STG.E.256, sm_100+). Halves LSU ops + L1tex queue entries per byte vs
// float4. Otherwise measured-best R3 shape: flat launch, block=256,
// 4 front-batched loads, streaming .cs policy.

struct f8 { float v[8]; };

__device__ __forceinline__ f8 ldg256_cs(const float* p) {
    f8 r;
    asm volatile(
        "ld.global.cs.v8.f32 {%0,%1,%2,%3,%4,%5,%6,%7}, [%8];"
        : "=f"(r.v[0]), "=f"(r.v[1]), "=f"(r.v[2]), "=f"(r.v[3]),
          "=f"(r.v[4]), "=f"(r.v[5]), "=f"(r.v[6]), "=f"(r.v[7])
        : "l"(p));
    return r;
}

__device__ __forceinline__ void stg256_cs(float* p, const f8& r) {
    asm volatile(
        "st.global.cs.v8.f32 [%0], {%1,%2,%3,%4,%5,%6,%7,%8};"
        :: "l"(p),
           "f"(r.v[0]), "f"(r.v[1]), "f"(r.v[2]), "f"(r.v[3]),
           "f"(r.v[4]), "f"(r.v[5]), "f"(r.v[6]), "f"(r.v[7])
        : "memory");
}

// One LIF step on 8 lanes; v updated in place, returns spikes.
__device__ __forceinline__ f8 lif_step8(const f8& xt, f8& v) {
    f8 s;
#pragma unroll
    for (int k = 0; k < 8; k++) {
        // exact reference order: v = (v + x) - v*0.5, FMA contraction blocked
        float nv = __fadd_rn(__fadd_rn(v.v[k], xt.v[k]), -__fmul_rn(v.v[k], 0.5f));
        float sk = (nv >= 1.0f) ? 1.0f : 0.0f;
        s.v[k] = sk;
        v.v[k] = (sk != 0.0f) ? 0.0f : nv;
    }
    return s;
}

__global__ void __launch_bounds__(256)
lif_kernel(const float* __restrict__ x, float* __restrict__ out, int n8) {
    int i = blockIdx.x * blockDim.x + threadIdx.x;
    if (i >= n8) return;

    const size_t n = (size_t)n8 * 8;        // floats per timestep
    const size_t off = (size_t)i * 8;

    // Front-batch all 4 independent 32B loads.
    f8 x0 = ldg256_cs(x + off);
    f8 x1 = ldg256_cs(x + n + off);
    f8 x2 = ldg256_cs(x + 2 * n + off);
    f8 x3 = ldg256_cs(x + 3 * n + off);

    f8 v;
#pragma unroll
    for (int k = 0; k < 8; k++) v.v[k] = 0.0f;

    f8 s0 = lif_step8(x0, v);
    stg256_cs(out + off, s0);
    f8 s1 = lif_step8(x1, v);
    stg256_cs(out + n + off, s1);
    f8 s2 = lif_step8(x2, v);
    stg256_cs(out + 2 * n + off, s2);
    f8 s3 = lif_step8(x3, v);
    stg256_cs(out + 3 * n + off, s3);
}

extern "C" void kernel_launch(void* const* d_in, const int* in_sizes, int n_in,
                              void* d_out, int out_size) {
    const float* x = (const float*)d_in[0];
    float* out = (float*)d_out;

    const int T = 4;
    int n_total = in_sizes[0];          // 67,108,864
    int n_per_step = n_total / T;       // 16,777,216
    int n8 = n_per_step / 8;            // 2,097,152 8-float lanes

    int threads = 256;
    int blocks = (n8 + threads - 1) / threads;   // 8192
    lif_kernel<<<blocks, threads>>>(x, out, n8);
}

// round 17
// speedup vs baseline: 1.0058x; 1.0058x over previous
#include <cuda_runtime.h>

// LIF, tau=2, hard reset to 0, decay_input=False:
//   v = (v + x_t) - v*0.5 ; s = (v>=1) ; out=s ; v = s?0:v
// Pure streaming: 268MB read + 268MB write, T=4 carried in registers.
// R15: final probe on the one axis with measured signal (CTA granularity:
// 256 > 512 >> persistent). block=128 -> 32768 small CTAs, max scheduler
// injection material, same 64 resident warps/SM. Per-thread structure is
// the measured-best R3 shape: 1 float4/thread, 4 front-batched __ldcs,
// __stcs stores, exact reference FP ordering.

__device__ __forceinline__ float4 lif_step(float4 xt, float4& v) {
    // exact reference order: v = (v + x) - v*0.5, FMA contraction blocked
    float nx = __fadd_rn(__fadd_rn(v.x, xt.x), -__fmul_rn(v.x, 0.5f));
    float ny = __fadd_rn(__fadd_rn(v.y, xt.y), -__fmul_rn(v.y, 0.5f));
    float nz = __fadd_rn(__fadd_rn(v.z, xt.z), -__fmul_rn(v.z, 0.5f));
    float nw = __fadd_rn(__fadd_rn(v.w, xt.w), -__fmul_rn(v.w, 0.5f));
    float4 s;
    s.x = (nx >= 1.0f) ? 1.0f : 0.0f;
    s.y = (ny >= 1.0f) ? 1.0f : 0.0f;
    s.z = (nz >= 1.0f) ? 1.0f : 0.0f;
    s.w = (nw >= 1.0f) ? 1.0f : 0.0f;
    v.x = (s.x != 0.0f) ? 0.0f : nx;
    v.y = (s.y != 0.0f) ? 0.0f : ny;
    v.z = (s.z != 0.0f) ? 0.0f : nz;
    v.w = (s.w != 0.0f) ? 0.0f : nw;
    return s;
}

__global__ void __launch_bounds__(128)
lif_kernel(const float4* __restrict__ x, float4* __restrict__ out, int n4) {
    int i = blockIdx.x * blockDim.x + threadIdx.x;
    if (i >= n4) return;

    const size_t n = (size_t)n4;

    // Front-batch all 4 independent loads: 4 LDG.128 in flight per thread.
    float4 x0 = __ldcs(&x[i]);
    float4 x1 = __ldcs(&x[n + i]);
    float4 x2 = __ldcs(&x[2 * n + i]);
    float4 x3 = __ldcs(&x[3 * n + i]);

    float4 v = make_float4(0.f, 0.f, 0.f, 0.f);

    float4 s0 = lif_step(x0, v);
    __stcs(&out[i], s0);
    float4 s1 = lif_step(x1, v);
    __stcs(&out[n + i], s1);
    float4 s2 = lif_step(x2, v);
    __stcs(&out[2 * n + i], s2);
    float4 s3 = lif_step(x3, v);
    __stcs(&out[3 * n + i], s3);
}

extern "C" void kernel_launch(void* const* d_in, const int* in_sizes, int n_in,
                              void* d_out, int out_size) {
    const float* x = (const float*)d_in[0];
    float* out = (float*)d_out;

    const int T = 4;
    int n_total = in_sizes[0];          // 67,108,864
    int n_per_step = n_total / T;       // 16,777,216
    int n4 = n_per_step / 4;            // 4,194,304 float4 lanes

    int threads = 128;
    int blocks = (n4 + threads - 1) / threads;   // 32768
    lif_kernel<<<blocks, threads>>>((const float4*)x, (float4*)out, n4);
}